// round 2
// baseline (speedup 1.0000x reference)
#include <cuda_runtime.h>
#include <cstdint>

#define BATCH 16
#define SPOS  1024
#define DIM   512
#define KC    12
#define KCTR  10
#define CS    8                 // cluster size = s-chunks per batch
#define SLEN  (SPOS / CS)       // 128
#define NT    512
#define NG    4                 // s-parity groups
#define ITERS (SLEN / NG)       // 32

typedef unsigned long long ull;

__device__ __forceinline__ void fma2(ull& acc, ull a, ull f) {
    asm("fma.rn.f32x2 %0, %1, %2, %0;" : "+l"(acc) : "l"(a), "l"(f));
}
__device__ __forceinline__ uint32_t s2u(const void* p) {
    uint32_t a;
    asm("{ .reg .u64 t; cvta.to.shared.u64 t, %1; cvt.u32.u64 %0, t; }" : "=r"(a) : "l"(p));
    return a;
}
__device__ __forceinline__ uint32_t mapa_u32(uint32_t a, uint32_t r) {
    uint32_t o;
    asm("mapa.shared::cluster.u32 %0, %1, %2;" : "=r"(o) : "r"(a), "r"(r));
    return o;
}
__device__ __forceinline__ ull ldc_u64(uint32_t a) {
    ull v;
    asm volatile("ld.shared::cluster.b64 %0, [%1];" : "=l"(v) : "r"(a));
    return v;
}
__device__ __forceinline__ float ldc_f32(uint32_t a) {
    float v;
    asm volatile("ld.shared::cluster.f32 %0, [%1];" : "=f"(v) : "r"(a));
    return v;
}
#define CLUSTER_SYNC() do { \
    asm volatile("barrier.cluster.arrive.aligned;" ::: "memory"); \
    asm volatile("barrier.cluster.wait.aligned;" ::: "memory"); } while (0)

__global__ __launch_bounds__(NT, 1) __cluster_dims__(CS, 1, 1)
void vlad_fused(const float* __restrict__ feat, const float* __restrict__ score,
                const float* __restrict__ cluster, float* __restrict__ out)
{
    __shared__ __align__(16) ull Ash[SLEN][KCTR];     // duplicated {a,a} pairs, 10 KB
    __shared__ __align__(16) ull buf[KCTR * 256];     // 20 KB: staging + cluster exchange
    __shared__ float aX[KCTR];                        // my chunk asum (peer-readable)
    __shared__ float sqX[KCTR];                       // my sq-slice partial (peer-readable)
    __shared__ float part80[80];
    __shared__ float asumTot[KCTR];
    __shared__ float sqTot[KCTR];

    const int tid = threadIdx.x;
    const int b = blockIdx.x >> 3;
    uint32_t rank;
    asm("mov.u32 %0, %%cluster_ctarank;" : "=r"(rank));
    const int s0 = (int)rank * SLEN;

    // ---- Phase 1: softmax over KC=12, store duplicated pairs for k<10 ----
    if (tid < SLEN) {
        const float* sp = score + (size_t)(b * SPOS + s0 + tid) * KC;
        float4 v0 = *(const float4*)sp;
        float4 v1 = *(const float4*)(sp + 4);
        float4 v2 = *(const float4*)(sp + 8);
        float v[KC] = {v0.x, v0.y, v0.z, v0.w, v1.x, v1.y, v1.z, v1.w,
                       v2.x, v2.y, v2.z, v2.w};
        float m = -1e30f;
        #pragma unroll
        for (int k = 0; k < KC; k++) m = fmaxf(m, v[k]);
        float sum = 0.f;
        #pragma unroll
        for (int k = 0; k < KC; k++) { v[k] = __expf(v[k] - m); sum += v[k]; }
        float inv = 1.f / sum;
        #pragma unroll
        for (int k = 0; k < KCTR; k++) {
            unsigned int u = __float_as_uint(v[k] * inv);
            Ash[tid][k] = ((ull)u << 32) | (ull)u;
        }
    }
    __syncthreads();

    // ---- Chunk asum (column sums of A over my 128 s) ----
    if (tid < 80) {
        int k = tid >> 3, p = tid & 7;
        float s = 0.f;
        #pragma unroll
        for (int i = 0; i < 16; i++)
            s += __uint_as_float((unsigned int)Ash[p * 16 + i][k]);
        part80[tid] = s;
    }
    __syncthreads();
    if (tid < KCTR) {
        float s = 0.f;
        #pragma unroll
        for (int p = 0; p < 8; p++) s += part80[tid * 8 + p];
        aX[tid] = s;
    }

    // ---- Main loop: group g handles s = g + 4i; thread owns 4 adjacent d ----
    const int g = tid >> 7, l = tid & 127;
    ull acc[KCTR][2];
    #pragma unroll
    for (int k = 0; k < KCTR; k++) { acc[k][0] = 0ull; acc[k][1] = 0ull; }

    const ull* fp = (const ull*)(feat + (size_t)(b * SPOS + s0 + g) * DIM) + l * 2;
    #pragma unroll 4
    for (int i = 0; i < ITERS; i++) {
        ulonglong2 f = *(const ulonglong2*)(fp + (size_t)i * NG * (DIM / 2));
        const ulonglong2* ar = (const ulonglong2*)Ash[g + i * NG];
        ulonglong2 a01 = ar[0], a23 = ar[1], a45 = ar[2], a67 = ar[3], a89 = ar[4];
        fma2(acc[0][0], a01.x, f.x); fma2(acc[0][1], a01.x, f.y);
        fma2(acc[1][0], a01.y, f.x); fma2(acc[1][1], a01.y, f.y);
        fma2(acc[2][0], a23.x, f.x); fma2(acc[2][1], a23.x, f.y);
        fma2(acc[3][0], a23.y, f.x); fma2(acc[3][1], a23.y, f.y);
        fma2(acc[4][0], a45.x, f.x); fma2(acc[4][1], a45.x, f.y);
        fma2(acc[5][0], a45.y, f.x); fma2(acc[5][1], a45.y, f.y);
        fma2(acc[6][0], a67.x, f.x); fma2(acc[6][1], a67.x, f.y);
        fma2(acc[7][0], a67.y, f.x); fma2(acc[7][1], a67.y, f.y);
        fma2(acc[8][0], a89.x, f.x); fma2(acc[8][1], a89.x, f.y);
        fma2(acc[9][0], a89.y, f.x); fma2(acc[9][1], a89.y, f.y);
    }

    // ---- Intra-CTA staged reduction of 4 group partials (buf as [128][20]) ----
    ull* row = buf + l * 20;
    if (g == 1) {
        #pragma unroll
        for (int k = 0; k < KCTR; k++) { row[2 * k] = acc[k][0]; row[2 * k + 1] = acc[k][1]; }
    }
    __syncthreads();
    if (g == 0) {
        #pragma unroll
        for (int k = 0; k < KCTR; k++) {
            fma2(acc[k][0], row[2 * k], 0x3f8000003f800000ull);     // acc += 1.0 * v
            fma2(acc[k][1], row[2 * k + 1], 0x3f8000003f800000ull);
        }
    }
    __syncthreads();
    if (g == 3) {
        #pragma unroll
        for (int k = 0; k < KCTR; k++) { row[2 * k] = acc[k][0]; row[2 * k + 1] = acc[k][1]; }
    }
    __syncthreads();
    if (g == 2) {
        #pragma unroll
        for (int k = 0; k < KCTR; k++) {
            fma2(acc[k][0], row[2 * k], 0x3f8000003f800000ull);
            fma2(acc[k][1], row[2 * k + 1], 0x3f8000003f800000ull);
        }
    }
    __syncthreads();
    if (g == 2) {
        #pragma unroll
        for (int k = 0; k < KCTR; k++) { row[2 * k] = acc[k][0]; row[2 * k + 1] = acc[k][1]; }
    }
    __syncthreads();
    if (g == 0) {
        #pragma unroll
        for (int k = 0; k < KCTR; k++) {
            fma2(acc[k][0], row[2 * k], 0x3f8000003f800000ull);
            fma2(acc[k][1], row[2 * k + 1], 0x3f8000003f800000ull);
        }
    }
    __syncthreads();  // all g0 reads complete before buf is overwritten
    if (g == 0) {     // write CTA total, k-major: buf[k*256 + dpair]
        #pragma unroll
        for (int k = 0; k < KCTR; k++) {
            buf[k * 256 + 2 * l]     = acc[k][0];
            buf[k * 256 + 2 * l + 1] = acc[k][1];
        }
    }
    CLUSTER_SYNC();   // exchange point: buf, aX visible cluster-wide

    // ---- Remote reduce: my CTA owns d-slice [rank*64, rank*64+64) for all k ----
    const uint32_t bufA = s2u(buf), aXA = s2u(aX), sqXA = s2u(sqX);
    const int k = tid >> 5, j = tid & 31;
    const bool act = tid < 320;

    float2 r2 = make_float2(0.f, 0.f);
    if (act) {
        int idx = k * 256 + (int)rank * 32 + j;
        #pragma unroll
        for (int p = 0; p < CS; p++) {
            int rr = ((int)rank + p) & 7;
            ull v = ldc_u64(mapa_u32(bufA + idx * 8, rr));
            r2.x += __uint_as_float((unsigned int)v);
            r2.y += __uint_as_float((unsigned int)(v >> 32));
        }
    }
    if (tid < 80) {  // gather remote chunk asums
        int kk = tid >> 3, rr = tid & 7;
        part80[tid] = ldc_f32(mapa_u32(aXA + kk * 4, (uint32_t)rr));
    }
    __syncthreads();
    if (tid < KCTR) {
        float s = 0.f;
        #pragma unroll
        for (int p = 0; p < 8; p++) s += part80[tid * 8 + p];
        asumTot[tid] = s;
    }
    __syncthreads();

    if (act) {
        float as = asumTot[k];
        float2 cl = *(const float2*)(cluster + k * DIM + (int)rank * 64 + j * 2);
        r2.x -= as * cl.x;
        r2.y -= as * cl.y;
        float sq = r2.x * r2.x + r2.y * r2.y;
        #pragma unroll
        for (int o = 16; o > 0; o >>= 1) sq += __shfl_xor_sync(0xffffffffu, sq, o);
        if (j == 0) sqX[k] = sq;   // warp k == threads [k*32, k*32+32)
    }
    CLUSTER_SYNC();   // sq partials visible cluster-wide

    if (tid < 80) {
        int kk = tid >> 3, rr = tid & 7;
        part80[tid] = ldc_f32(mapa_u32(sqXA + kk * 4, (uint32_t)rr));
    }
    __syncthreads();
    if (tid < KCTR) {
        float s = 0.f;
        #pragma unroll
        for (int p = 0; p < 8; p++) s += part80[tid * 8 + p];
        sqTot[tid] = s;
    }
    __syncthreads();

    if (act) {
        float iv = rsqrtf(fmaxf(sqTot[k], 1e-12f));
        float2 o2 = make_float2(r2.x * iv, r2.y * iv);
        *(float2*)(out + (size_t)b * (KCTR * DIM) + k * DIM + (int)rank * 64 + j * 2) = o2;
    }
    CLUSTER_SYNC();   // no CTA exits while peers may still read its smem
}

extern "C" void kernel_launch(void* const* d_in, const int* in_sizes, int n_in,
                              void* d_out, int out_size) {
    const float* feat    = (const float*)d_in[0];  // (16,16,64,512) f32
    const float* score   = (const float*)d_in[1];  // (16,16,64,12)  f32
    const float* cluster = (const float*)d_in[2];  // (12,512)       f32
    float* out = (float*)d_out;                    // (16,5120)      f32

    vlad_fused<<<BATCH * CS, NT>>>(feat, score, cluster, out);
}

// round 3
// speedup vs baseline: 1.3619x; 1.3619x over previous
#include <cuda_runtime.h>
#include <cstdint>

#define B     16
#define S     1024
#define D     512
#define KC    12
#define K     10
#define NDS   16          // d-slices per batch
#define DSW   32          // d per slice
#define NT    256
#define TILES 4
#define TS    256         // s per tile
#define NSG   32          // s-groups (threads: sg = tid>>3, dp = tid&7)
#define SITER (TS / NSG)  // 8 s per thread per tile

typedef unsigned long long ull;
#define ONE2 0x3f8000003f800000ull

__device__ float g_sqpart[B * K * NDS];

__device__ __forceinline__ void fma2(ull& acc, ull a, ull f) {
    asm("fma.rn.f32x2 %0, %1, %2, %0;" : "+l"(acc) : "l"(a), "l"(f));
}

__global__ __launch_bounds__(NT, 2)
void vlad_main(const float* __restrict__ feat, const float* __restrict__ score,
               const float* __restrict__ cluster, float* __restrict__ out)
{
    // 20 KB, dual-purpose: softmax pairs per tile / final sg-reduction buffer
    __shared__ __align__(16) ull Ash[TS][K];
    __shared__ float wsum[8][K];
    __shared__ float asumS[K];

    const int tid = threadIdx.x;
    const int b  = blockIdx.x >> 4;
    const int ds = blockIdx.x & 15;
    const int d0 = ds * DSW;
    const int dp = tid & 7;          // which 4-float group within the 32-d slice
    const int sg = tid >> 3;         // s-group 0..31

    ull acc[K][2];
    #pragma unroll
    for (int k = 0; k < K; k++) { acc[k][0] = 0ull; acc[k][1] = 0ull; }
    float asumr[K];
    #pragma unroll
    for (int k = 0; k < K; k++) asumr[k] = 0.f;

    const float* fbase = feat + (size_t)b * S * D + d0 + dp * 4;

    for (int T = 0; T < TILES; T++) {
        // ---- softmax for s = T*256 + tid (all 256 threads, one s each) ----
        {
            const float* sp = score + ((size_t)(b * S) + T * TS + tid) * KC;
            float4 v0 = *(const float4*)sp;
            float4 v1 = *(const float4*)(sp + 4);
            float4 v2 = *(const float4*)(sp + 8);
            float v[KC] = {v0.x, v0.y, v0.z, v0.w, v1.x, v1.y, v1.z, v1.w,
                           v2.x, v2.y, v2.z, v2.w};
            float m = -1e30f;
            #pragma unroll
            for (int k = 0; k < KC; k++) m = fmaxf(m, v[k]);
            float sum = 0.f;
            #pragma unroll
            for (int k = 0; k < KC; k++) { v[k] = __expf(v[k] - m); sum += v[k]; }
            float inv = 1.f / sum;
            #pragma unroll
            for (int k = 0; k < K; k++) {
                float a = v[k] * inv;
                asumr[k] += a;
                unsigned int u = __float_as_uint(a);
                Ash[tid][k] = ((ull)u << 32) | (ull)u;
            }
        }
        __syncthreads();

        // ---- main loop: s = sg + 32*i within tile; thread owns 4 d ----
        const float* fr = fbase + ((size_t)(T * TS) + sg) * D;
        #pragma unroll 4
        for (int i = 0; i < SITER; i++) {
            ulonglong2 f = *(const ulonglong2*)(fr + (size_t)i * NSG * D);
            const ulonglong2* ar = (const ulonglong2*)Ash[sg + i * NSG];
            ulonglong2 a01 = ar[0], a23 = ar[1], a45 = ar[2], a67 = ar[3], a89 = ar[4];
            fma2(acc[0][0], a01.x, f.x); fma2(acc[0][1], a01.x, f.y);
            fma2(acc[1][0], a01.y, f.x); fma2(acc[1][1], a01.y, f.y);
            fma2(acc[2][0], a23.x, f.x); fma2(acc[2][1], a23.x, f.y);
            fma2(acc[3][0], a23.y, f.x); fma2(acc[3][1], a23.y, f.y);
            fma2(acc[4][0], a45.x, f.x); fma2(acc[4][1], a45.x, f.y);
            fma2(acc[5][0], a45.y, f.x); fma2(acc[5][1], a45.y, f.y);
            fma2(acc[6][0], a67.x, f.x); fma2(acc[6][1], a67.x, f.y);
            fma2(acc[7][0], a67.y, f.x); fma2(acc[7][1], a67.y, f.y);
            fma2(acc[8][0], a89.x, f.x); fma2(acc[8][1], a89.x, f.y);
            fma2(acc[9][0], a89.y, f.x); fma2(acc[9][1], a89.y, f.y);
        }
        __syncthreads();   // protect Ash before next tile overwrites it
    }

    // ---- block-reduce asum (each of 1024 s counted exactly once) ----
    #pragma unroll
    for (int k = 0; k < K; k++) {
        float v = asumr[k];
        #pragma unroll
        for (int o = 16; o > 0; o >>= 1) v += __shfl_xor_sync(0xffffffffu, v, o);
        if ((tid & 31) == 0) wsum[tid >> 5][k] = v;
    }
    __syncthreads();
    if (tid < K) {
        float s = 0.f;
        #pragma unroll
        for (int w = 0; w < 8; w++) s += wsum[w][tid];
        asumS[tid] = s;
    }

    // ---- reduce acc over the 32 s-groups (tree in smem, reusing Ash) ----
    ull* buf = &Ash[0][0];            // [16*8][20] ull = 20 KB
    ull* accp = &acc[0][0];
    #pragma unroll
    for (int h = 16; h > 0; h >>= 1) {
        __syncthreads();
        if (sg >= h && sg < 2 * h) {
            ull* row = buf + ((sg - h) * 8 + dp) * 20;
            #pragma unroll
            for (int j = 0; j < 20; j++) row[j] = accp[j];
        }
        __syncthreads();
        if (sg < h) {
            const ull* row = buf + (sg * 8 + dp) * 20;
            #pragma unroll
            for (int j = 0; j < 20; j++) fma2(accp[j], row[j], ONE2);
        }
    }

    // ---- epilogue: 8 threads (sg==0) hold totals for 10k x 4d ----
    if (sg == 0) {
        #pragma unroll
        for (int k = 0; k < K; k++) {
            float as = asumS[k];
            float4 cl = *(const float4*)(cluster + k * D + d0 + dp * 4);
            float rx = __uint_as_float((unsigned int)acc[k][0])        - as * cl.x;
            float ry = __uint_as_float((unsigned int)(acc[k][0] >> 32)) - as * cl.y;
            float rz = __uint_as_float((unsigned int)acc[k][1])        - as * cl.z;
            float rw = __uint_as_float((unsigned int)(acc[k][1] >> 32)) - as * cl.w;
            *(float4*)(out + ((size_t)(b * K) + k) * D + d0 + dp * 4) =
                make_float4(rx, ry, rz, rw);
            float sq = rx * rx + ry * ry + rz * rz + rw * rw;
            sq += __shfl_xor_sync(0x000000ffu, sq, 4);
            sq += __shfl_xor_sync(0x000000ffu, sq, 2);
            sq += __shfl_xor_sync(0x000000ffu, sq, 1);
            if (dp == 0) g_sqpart[(b * K + k) * NDS + ds] = sq;
        }
    }
}

__global__ __launch_bounds__(128, 8)
void vlad_norm(float* __restrict__ out)
{
    const int b = blockIdx.x / K;
    const int k = blockIdx.x % K;
    const int tid = threadIdx.x;

    float s = 0.f;
    #pragma unroll
    for (int p = 0; p < NDS; p++) s += g_sqpart[(b * K + k) * NDS + p];
    float inv = rsqrtf(fmaxf(s, 1e-12f));

    float4* p = (float4*)(out + ((size_t)(b * K) + k) * D) + tid;
    float4 v = *p;
    v.x *= inv; v.y *= inv; v.z *= inv; v.w *= inv;
    *p = v;
}

extern "C" void kernel_launch(void* const* d_in, const int* in_sizes, int n_in,
                              void* d_out, int out_size) {
    const float* feat    = (const float*)d_in[0];  // (16,16,64,512) f32
    const float* score   = (const float*)d_in[1];  // (16,16,64,12)  f32
    const float* cluster = (const float*)d_in[2];  // (12,512)       f32
    float* out = (float*)d_out;                    // (16,5120)      f32

    vlad_main<<<B * NDS, NT>>>(feat, score, cluster, out);
    vlad_norm<<<B * K, 128>>>(out);
}

// round 4
// speedup vs baseline: 1.3826x; 1.0152x over previous
#include <cuda_runtime.h>
#include <cstdint>

#define B     16
#define S     1024
#define D     512
#define KC    12
#define K     10
#define NDS   16          // d-slices per batch
#define DSW   32          // d per slice
#define NT    256
#define TILES 2
#define TS    512         // s per tile
#define NSG   32          // s-groups (threads: sg = tid>>3, dp = tid&7)
#define SITER (TS / NSG)  // 16 s per thread per tile

typedef unsigned long long ull;
#define ONE2 0x3f8000003f800000ull

__device__ float g_sqpart[B][K][NDS];
__device__ int   g_cnt[B];

__device__ __forceinline__ void fma2(ull& acc, ull a, ull f) {
    asm("fma.rn.f32x2 %0, %1, %2, %0;" : "+l"(acc) : "l"(a), "l"(f));
}

__global__ __launch_bounds__(NT, 2)
void vlad_fused(const float* __restrict__ feat, const float* __restrict__ score,
                const float* __restrict__ cluster, float* __restrict__ out)
{
    // 40 KB, dual-purpose: softmax pairs per tile / final sg-reduction buffer
    __shared__ __align__(16) ull Ash[TS][K];
    __shared__ float wsum[8][K];
    __shared__ float asumS[K];
    __shared__ float invS[K];
    __shared__ int   isLast;

    const int tid = threadIdx.x;
    const int b  = blockIdx.x >> 4;
    const int ds = blockIdx.x & 15;
    const int d0 = ds * DSW;
    const int dp = tid & 7;          // 4-float group within the 32-d slice
    const int sg = tid >> 3;         // s-group 0..31

    ull acc[K][2];
    #pragma unroll
    for (int k = 0; k < K; k++) { acc[k][0] = 0ull; acc[k][1] = 0ull; }
    float asumr[K];
    #pragma unroll
    for (int k = 0; k < K; k++) asumr[k] = 0.f;

    const float* fbase = feat + (size_t)b * S * D + d0 + dp * 4;

    for (int T = 0; T < TILES; T++) {
        // ---- softmax: 2 rows per thread (rows tid and tid+256 of this tile) ----
        #pragma unroll
        for (int r = 0; r < 2; r++) {
            const int row = tid + r * NT;
            const float* sp = score + ((size_t)(b * S) + T * TS + row) * KC;
            float4 v0 = *(const float4*)sp;
            float4 v1 = *(const float4*)(sp + 4);
            float4 v2 = *(const float4*)(sp + 8);
            float v[KC] = {v0.x, v0.y, v0.z, v0.w, v1.x, v1.y, v1.z, v1.w,
                           v2.x, v2.y, v2.z, v2.w};
            float sum = 0.f;
            #pragma unroll
            for (int k = 0; k < KC; k++) { v[k] = __expf(v[k]); sum += v[k]; }
            float inv = 1.f / sum;
            #pragma unroll
            for (int k = 0; k < K; k++) {
                float a = v[k] * inv;
                asumr[k] += a;
                unsigned int u = __float_as_uint(a);
                Ash[row][k] = ((ull)u << 32) | (ull)u;
            }
        }
        __syncthreads();

        // ---- main loop: s = sg + 32*i within tile; thread owns 4 d ----
        const float* fr = fbase + ((size_t)(T * TS) + sg) * D;
        #pragma unroll 4
        for (int i = 0; i < SITER; i++) {
            ulonglong2 f = *(const ulonglong2*)(fr + (size_t)i * NSG * D);
            const ulonglong2* ar = (const ulonglong2*)Ash[sg + i * NSG];
            ulonglong2 a01 = ar[0], a23 = ar[1], a45 = ar[2], a67 = ar[3], a89 = ar[4];
            fma2(acc[0][0], a01.x, f.x); fma2(acc[0][1], a01.x, f.y);
            fma2(acc[1][0], a01.y, f.x); fma2(acc[1][1], a01.y, f.y);
            fma2(acc[2][0], a23.x, f.x); fma2(acc[2][1], a23.x, f.y);
            fma2(acc[3][0], a23.y, f.x); fma2(acc[3][1], a23.y, f.y);
            fma2(acc[4][0], a45.x, f.x); fma2(acc[4][1], a45.x, f.y);
            fma2(acc[5][0], a45.y, f.x); fma2(acc[5][1], a45.y, f.y);
            fma2(acc[6][0], a67.x, f.x); fma2(acc[6][1], a67.x, f.y);
            fma2(acc[7][0], a67.y, f.x); fma2(acc[7][1], a67.y, f.y);
            fma2(acc[8][0], a89.x, f.x); fma2(acc[8][1], a89.x, f.y);
            fma2(acc[9][0], a89.y, f.x); fma2(acc[9][1], a89.y, f.y);
        }
        __syncthreads();   // protect Ash before next tile / reduction reuse
    }

    // ---- block-reduce asum (each of 1024 s counted exactly once) ----
    #pragma unroll
    for (int k = 0; k < K; k++) {
        float v = asumr[k];
        #pragma unroll
        for (int o = 16; o > 0; o >>= 1) v += __shfl_xor_sync(0xffffffffu, v, o);
        if ((tid & 31) == 0) wsum[tid >> 5][k] = v;
    }
    __syncthreads();
    if (tid < K) {
        float s = 0.f;
        #pragma unroll
        for (int w = 0; w < 8; w++) s += wsum[w][tid];
        asumS[tid] = s;
    }

    // ---- reduce acc over the 32 s-groups (tree in smem, reusing Ash) ----
    ull* buf = &Ash[0][0];            // [16*8][20] ull fits in 40 KB
    ull* accp = &acc[0][0];
    #pragma unroll
    for (int h = 16; h > 0; h >>= 1) {
        __syncthreads();
        if (sg >= h && sg < 2 * h) {
            ull* row = buf + ((sg - h) * 8 + dp) * 20;
            #pragma unroll
            for (int j = 0; j < 20; j++) row[j] = accp[j];
        }
        __syncthreads();
        if (sg < h) {
            const ull* row = buf + (sg * 8 + dp) * 20;
            #pragma unroll
            for (int j = 0; j < 20; j++) fma2(accp[j], row[j], ONE2);
        }
    }

    // ---- epilogue: 8 threads (sg==0) hold totals for 10k x 4d ----
    if (sg == 0) {
        #pragma unroll
        for (int k = 0; k < K; k++) {
            float as = asumS[k];
            float4 cl = *(const float4*)(cluster + k * D + d0 + dp * 4);
            float rx = __uint_as_float((unsigned int)acc[k][0])         - as * cl.x;
            float ry = __uint_as_float((unsigned int)(acc[k][0] >> 32)) - as * cl.y;
            float rz = __uint_as_float((unsigned int)acc[k][1])         - as * cl.z;
            float rw = __uint_as_float((unsigned int)(acc[k][1] >> 32)) - as * cl.w;
            *(float4*)(out + ((size_t)(b * K) + k) * D + d0 + dp * 4) =
                make_float4(rx, ry, rz, rw);
            float sq = rx * rx + ry * ry + rz * rz + rw * rw;
            sq += __shfl_xor_sync(0x000000ffu, sq, 4);
            sq += __shfl_xor_sync(0x000000ffu, sq, 2);
            sq += __shfl_xor_sync(0x000000ffu, sq, 1);
            if (dp == 0) g_sqpart[b][k][ds] = sq;
        }
    }

    // ---- last CTA of this batch performs the L2 normalization ----
    __threadfence();                 // publish out + g_sqpart before count
    __syncthreads();
    if (tid == 0) {
        int old = atomicAdd(&g_cnt[b], 1);
        isLast = (old == NDS - 1);
    }
    __syncthreads();
    if (isLast) {
        __threadfence();             // acquire: see peers' out/sqpart writes
        if (tid < K) {
            float s = 0.f;
            #pragma unroll
            for (int p = 0; p < NDS; p++) s += g_sqpart[b][tid][p];
            invS[tid] = rsqrtf(fmaxf(s, 1e-12f));
        }
        __syncthreads();
        float4* o4 = (float4*)out + (size_t)b * (K * D / 4);   // 1280 float4
        #pragma unroll
        for (int j = 0; j < 5; j++) {
            int idx = tid + j * NT;          // 0..1279
            float iv = invS[idx >> 7];       // 128 float4 per k
            float4 v = o4[idx];
            v.x *= iv; v.y *= iv; v.z *= iv; v.w *= iv;
            o4[idx] = v;
        }
        if (tid == 0) g_cnt[b] = 0;          // reset for next graph replay
    }
}

extern "C" void kernel_launch(void* const* d_in, const int* in_sizes, int n_in,
                              void* d_out, int out_size) {
    const float* feat    = (const float*)d_in[0];  // (16,16,64,512) f32
    const float* score   = (const float*)d_in[1];  // (16,16,64,12)  f32
    const float* cluster = (const float*)d_in[2];  // (12,512)       f32
    float* out = (float*)d_out;                    // (16,5120)      f32

    vlad_fused<<<B * NDS, NT>>>(feat, score, cluster, out);
}